// round 1
// baseline (speedup 1.0000x reference)
#include <cuda_runtime.h>
#include <math.h>

#define NPTS   16384
#define BATCH  2
#define HBEV   200
#define WBEV   176
#define CBEV   256
#define HW     (HBEV*WBEV)
#define KTOT   2048
#define NROWS  (BATCH*KTOT)
#define CMPN   8192
#define FULLM  0xffffffffu

// ---------------- static device scratch (no allocations allowed) ----------------
__device__ float4 g_pts[BATCH*NPTS];        // SoA points: x,y,z,intensity
__device__ float4 g_cmp[6*CMPN];            // per (batch,band) compacted xyz, padded with 1e15
__device__ float  g_sfT[(size_t)BATCH*HW*CBEV]; // spatial features transposed to [b][hw][c]
__device__ float  g_kp[NROWS*3];            // selected keypoint coords

// ---------------- prep: AoS points -> float4 SoA ----------------
__global__ void prep_pts_kernel(const float* __restrict__ points) {
    int i = blockIdx.x*blockDim.x + threadIdx.x;
    if (i < BATCH*NPTS) {
        const float* p = points + (size_t)i*5;
        g_pts[i] = make_float4(p[1], p[2], p[3], p[4]);
    }
}

// ---------------- transpose spatial_features [b][c][hw] -> [b][hw][c] ----------------
__global__ void transpose_kernel(const float* __restrict__ sf) {
    __shared__ float tile[32][33];
    int b  = blockIdx.z;
    int hw0 = blockIdx.x*32, c0 = blockIdx.y*32;
    const float* src = sf   + (size_t)b*CBEV*HW;
    float*       dst = g_sfT + (size_t)b*HW*CBEV;
    #pragma unroll
    for (int j = threadIdx.y; j < 32; j += 8)
        tile[j][threadIdx.x] = src[(size_t)(c0+j)*HW + hw0 + threadIdx.x];
    __syncthreads();
    #pragma unroll
    for (int j = threadIdx.y; j < 32; j += 8)
        dst[(size_t)(hw0+j)*CBEV + c0 + threadIdx.x] = tile[threadIdx.x][j];
}

// ---------------- stable band compaction (order-preserving) ----------------
__global__ void __launch_bounds__(1024) compact_kernel(const float* __restrict__ rng) {
    int run = blockIdx.x, b = run/3, band = run - b*3;
    int t = threadIdx.x;
    const float* R = rng + (size_t)b*NPTS;
    int base = t*16;
    unsigned bits = 0; int cnt = 0;
    #pragma unroll
    for (int u = 0; u < 16; u++) {
        float r = R[base + u];
        bool sh = (r > 0.0f) && (r < 25.0f);
        bool lg = (r > 45.0f);
        bool v = (band == 0) ? sh : ((band == 2) ? lg : (!lg && !sh));
        if (v) { bits |= (1u << u); cnt++; }
    }
    __shared__ int wsum[32];
    __shared__ int s_tot;
    int lane = t & 31, warp = t >> 5;
    int inc = cnt;
    #pragma unroll
    for (int off = 1; off < 32; off <<= 1) {
        int o = __shfl_up_sync(FULLM, inc, off);
        if (lane >= off) inc += o;
    }
    if (lane == 31) wsum[warp] = inc;
    __syncthreads();
    if (warp == 0) {
        int v = wsum[lane];
        #pragma unroll
        for (int off = 1; off < 32; off <<= 1) {
            int o = __shfl_up_sync(FULLM, v, off);
            if (lane >= off) v += o;
        }
        wsum[lane] = v;
        if (lane == 31) s_tot = v;
    }
    __syncthreads();
    int off0 = inc - cnt + (warp ? wsum[warp-1] : 0);
    float4* dst = g_cmp + run*CMPN;
    const float4* src = g_pts + (size_t)b*NPTS;
    #pragma unroll
    for (int u = 0; u < 16; u++) {
        if ((bits >> u) & 1u) {
            if (off0 < CMPN) dst[off0] = src[base + u];
            off0++;
        }
    }
    int M = s_tot;
    for (int i = M + t; i < CMPN; i += 1024)
        dst[i] = make_float4(1e15f, 1e15f, 1e15f, 0.f); // pad => dist stays -1, never chosen
}

// ---------------- furthest point sampling: fully register-resident ----------------
__global__ void __launch_bounds__(1024,1) fps_kernel(float* __restrict__ coords_out) {
    int run = blockIdx.x, b = run/3, band = run - b*3;
    int K = (band == 0) ? 1024 : 512;
    int kpbase = b*KTOT + (band==0 ? 0 : (band==1 ? 1024 : 1536));
    int t = threadIdx.x;
    const float4* cm = g_cmp + run*CMPN;

    float X[8], Y[8], Z[8], D[8];
    #pragma unroll
    for (int j = 0; j < 8; j++) {
        float4 p = cm[j*1024 + t];
        X[j] = p.x; Y[j] = p.y; Z[j] = p.z;
        D[j] = (p.x > 1e14f) ? -1.0f : 1e10f;   // pads permanently at -1 (matches invalid = -1)
    }

    __shared__ float sc[3];
    __shared__ float sv[32];
    __shared__ int   si[32];
    __shared__ int   ssel;

    int sel = 0;  // first valid point = compacted index 0 (argmax of boolean mask)
    for (int k = 0; k < K; k++) {
        int ot = sel & 1023, oj = sel >> 10;
        if (t == ot) {
            float x = X[0], y = Y[0], z = Z[0];
            #pragma unroll
            for (int j = 1; j < 8; j++) if (j == oj) { x = X[j]; y = Y[j]; z = Z[j]; }
            sc[0] = x; sc[1] = y; sc[2] = z;
            int rowi = kpbase + k;
            g_kp[rowi*3+0] = x; g_kp[rowi*3+1] = y; g_kp[rowi*3+2] = z;
            coords_out[rowi*4+0] = (float)b;
            coords_out[rowi*4+1] = x; coords_out[rowi*4+2] = y; coords_out[rowi*4+3] = z;
        }
        __syncthreads();
        float lx = sc[0], ly = sc[1], lz = sc[2];
        if (k == K-1) break;

        float best = -2.0f; int bi = 0x7fffffff;
        #pragma unroll
        for (int j = 0; j < 8; j++) {
            float dx = X[j] - lx, dy = Y[j] - ly, dz = Z[j] - lz;
            // no FMA contraction: match ((dx*dx + dy*dy) + dz*dz) exactly
            float d = __fadd_rn(__fadd_rn(__fmul_rn(dx,dx), __fmul_rn(dy,dy)), __fmul_rn(dz,dz));
            float nd = fminf(D[j], d);
            D[j] = nd;
            if (nd > best) { best = nd; bi = j*1024 + t; }  // strict > => first occurrence
        }
        #pragma unroll
        for (int off = 16; off; off >>= 1) {
            float ov = __shfl_down_sync(FULLM, best, off);
            int   oi = __shfl_down_sync(FULLM, bi,   off);
            if (ov > best || (ov == best && oi < bi)) { best = ov; bi = oi; }
        }
        if ((t & 31) == 0) { sv[t>>5] = best; si[t>>5] = bi; }
        __syncthreads();
        if (t < 32) {
            best = sv[t]; bi = si[t];
            #pragma unroll
            for (int off = 16; off; off >>= 1) {
                float ov = __shfl_down_sync(FULLM, best, off);
                int   oi = __shfl_down_sync(FULLM, bi,   off);
                if (ov > best || (ov == best && oi < bi)) { best = ov; bi = oi; }
            }
            if (t == 0) ssel = bi;
        }
        __syncthreads();
        sel = ssel;
    }
}

// ---------------- BEV bilinear gather (coalesced on channels after transpose) ----------------
__global__ void bev_kernel(float* __restrict__ outFeats) {
    int row = blockIdx.x;
    int b = row >> 11;
    float kx = g_kp[row*3+0], ky = g_kp[row*3+1];
    float xi = ((kx - 0.0f)    / 0.05f) / 8.0f;   // IEEE division (matches reference)
    float yi = ((ky - (-40.0f)) / 0.05f) / 8.0f;
    int x0 = (int)floorf(xi); int x1 = x0 + 1;
    int y0 = (int)floorf(yi); int y1 = y0 + 1;
    x0 = min(max(x0, 0), WBEV-1); x1 = min(max(x1, 0), WBEV-1);
    y0 = min(max(y0, 0), HBEV-1); y1 = min(max(y1, 0), HBEV-1);
    float x0f = (float)x0, x1f = (float)x1, y0f = (float)y0, y1f = (float)y1;
    float wa = (x1f - xi)*(y1f - yi);
    float wb = (x1f - xi)*(yi - y0f);
    float wc = (xi - x0f)*(y1f - yi);
    float wd = (xi - x0f)*(yi - y0f);
    const float* bb = g_sfT + (size_t)b*HW*CBEV;
    const float* Ia = bb + (size_t)(y0*WBEV + x0)*CBEV;
    const float* Ib = bb + (size_t)(y1*WBEV + x0)*CBEV;
    const float* Ic = bb + (size_t)(y0*WBEV + x1)*CBEV;
    const float* Id = bb + (size_t)(y1*WBEV + x1)*CBEV;
    int c = threadIdx.x;
    outFeats[(size_t)row*288 + c] = Ia[c]*wa + Ib[c]*wb + Ic[c]*wc + Id[c]*wd;
}

// ---------------- ball query (ordered first-16, 2 radii) + MLP + maxpool ----------------
__global__ void __launch_bounds__(128) sa_kernel(
        const float* __restrict__ w0, const float* __restrict__ bn0,
        const float* __restrict__ w1, const float* __restrict__ bn1,
        float* __restrict__ outFeats) {
    __shared__ float sw0[2*4*16];
    __shared__ float sw1[2*16*16];
    __shared__ float sb0s[32], sb0m[32], sb0b[32];
    __shared__ float sb1s[32], sb1m[32], sb1b[32];
    __shared__ int   sidx[4][2][16];
    int tid = threadIdx.x;
    sw0[tid] = w0[tid];
    for (int i = tid; i < 512; i += 128) sw1[i] = w1[i];
    if (tid < 32) {
        int br = tid >> 4, c = tid & 15;
        float g = bn0[br*64 + c], be = bn0[br*64+16+c], m = bn0[br*64+32+c], v = bn0[br*64+48+c];
        sb0s[tid] = g * (1.0f/sqrtf(v + 1e-5f)); sb0m[tid] = m; sb0b[tid] = be;
        g = bn1[br*64 + c]; be = bn1[br*64+16+c]; m = bn1[br*64+32+c]; v = bn1[br*64+48+c];
        sb1s[tid] = g * (1.0f/sqrtf(v + 1e-5f)); sb1m[tid] = m; sb1b[tid] = be;
    }
    __syncthreads();

    int w = tid >> 5, lane = tid & 31;
    int row = blockIdx.x*4 + w;
    int b = row >> 11;
    float kx = g_kp[row*3], ky = g_kp[row*3+1], kz = g_kp[row*3+2];
    const float4* P = g_pts + (size_t)b*NPTS;
    unsigned lt = (1u << lane) - 1u;

    int c1 = 0, c2 = 0;
    for (int base = 0; base < NPTS; base += 32) {
        float4 p = P[base + lane];
        float dx = kx - p.x, dy = ky - p.y, dz = kz - p.z;
        float d2 = __fadd_rn(__fadd_rn(__fmul_rn(dx,dx), __fmul_rn(dy,dy)), __fmul_rn(dz,dz));
        bool v1 = d2 < 1.0f, v2 = d2 < 4.0f;
        unsigned m1 = __ballot_sync(FULLM, v1);
        unsigned m2 = __ballot_sync(FULLM, v2);
        if (c1 < 16 && m1) {
            int rk = __popc(m1 & lt);
            if (v1 && c1 + rk < 16) sidx[w][0][c1+rk] = base + lane;
            c1 = min(c1 + __popc(m1), 16);
        }
        if (c2 < 16 && m2) {
            int rk = __popc(m2 & lt);
            if (v2 && c2 + rk < 16) sidx[w][1][c2+rk] = base + lane;
            c2 = min(c2 + __popc(m2), 16);
        }
        if (c1 >= 16 && c2 >= 16) break;
    }
    __syncwarp();

    int rI = lane >> 4, s = lane & 15;
    int cnt = rI ? c2 : c1;
    float gx = 0.f, gy = 0.f, gz = 0.f, gi = 0.f;
    if (cnt > 0) {
        int id = sidx[w][rI][(s < cnt) ? s : 0];   // pad with first neighbor (matches reference)
        float4 p = P[id];
        gx = p.x - kx; gy = p.y - ky; gz = p.z - kz; gi = p.w;
    }
    const float* W0  = sw0  + rI*64;
    const float* W1  = sw1  + rI*256;
    const float* B0s = sb0s + rI*16; const float* B0m = sb0m + rI*16; const float* B0b = sb0b + rI*16;
    const float* B1s = sb1s + rI*16; const float* B1m = sb1m + rI*16; const float* B1b = sb1b + rI*16;

    float h1[16];
    #pragma unroll
    for (int c = 0; c < 16; c++) {
        float a = gx*W0[c] + gy*W0[16+c] + gz*W0[32+c] + gi*W0[48+c];
        h1[c] = fmaxf((a - B0m[c])*B0s[c] + B0b[c], 0.0f);
    }
    float h2[16];
    #pragma unroll
    for (int c = 0; c < 16; c++) {
        float a = 0.f;
        #pragma unroll
        for (int k = 0; k < 16; k++) a += h1[k]*W1[k*16 + c];
        h2[c] = fmaxf((a - B1m[c])*B1s[c] + B1b[c], 0.0f);
    }
    #pragma unroll
    for (int off = 8; off; off >>= 1) {
        #pragma unroll
        for (int c = 0; c < 16; c++)
            h2[c] = fmaxf(h2[c], __shfl_xor_sync(FULLM, h2[c], off));
    }
    if (s == 0) {
        float* o = outFeats + (size_t)row*288 + 256 + rI*16;
        #pragma unroll
        for (int c = 0; c < 16; c++) o[c] = h2[c];
    }
}

// ---------------- fusion: [4096,288] @ [288,128] + BN + ReLU ----------------
__global__ void __launch_bounds__(128) fusion_kernel(
        const float* __restrict__ feats, const float* __restrict__ fw,
        const float* __restrict__ fbn, float* __restrict__ out) {
    __shared__ float sr[16*288];
    int tid = threadIdx.x;
    size_t row0 = (size_t)blockIdx.x * 16;
    for (int i = tid; i < 16*288; i += 128) sr[i] = feats[row0*288 + i];
    __syncthreads();
    float acc[16];
    #pragma unroll
    for (int r = 0; r < 16; r++) acc[r] = 0.f;
    for (int k = 0; k < 288; k++) {
        float wv = fw[(size_t)k*128 + tid];
        #pragma unroll
        for (int r = 0; r < 16; r++) acc[r] += sr[r*288 + k] * wv;
    }
    float g = fbn[tid], be = fbn[128+tid], m = fbn[256+tid], v = fbn[384+tid];
    float sc = g * (1.0f/sqrtf(v + 1e-5f));
    #pragma unroll
    for (int r = 0; r < 16; r++)
        out[(row0 + r)*128 + tid] = fmaxf((acc[r] - m)*sc + be, 0.f);
}

// ---------------- launch ----------------
extern "C" void kernel_launch(void* const* d_in, const int* in_sizes, int n_in,
                              void* d_out, int out_size) {
    const float* points = (const float*)d_in[0];
    const float* rng    = (const float*)d_in[1];
    const float* sf     = (const float*)d_in[2];
    const float* sa_w0  = (const float*)d_in[3];
    const float* sa_bn0 = (const float*)d_in[4];
    const float* sa_w1  = (const float*)d_in[5];
    const float* sa_bn1 = (const float*)d_in[6];
    const float* fw     = (const float*)d_in[7];
    const float* fbn    = (const float*)d_in[8];
    float* out = (float*)d_out;

    float* fused  = out;                                          // [4096,128]
    float* feats  = out + (size_t)NROWS*128;                      // [4096,288]
    float* coords = out + (size_t)NROWS*128 + (size_t)NROWS*288;  // [4096,4]

    prep_pts_kernel<<<(BATCH*NPTS + 255)/256, 256>>>(points);
    transpose_kernel<<<dim3(HW/32, CBEV/32, BATCH), dim3(32, 8)>>>(sf);
    compact_kernel<<<6, 1024>>>(rng);
    fps_kernel<<<6, 1024>>>(coords);
    bev_kernel<<<NROWS, 256>>>(feats);
    sa_kernel<<<NROWS/4, 128>>>(sa_w0, sa_bn0, sa_w1, sa_bn1, feats);
    fusion_kernel<<<NROWS/16, 128>>>(feats, fw, fbn, fused);
}

// round 2
// speedup vs baseline: 1.1383x; 1.1383x over previous
#include <cuda_runtime.h>
#include <math.h>

#define NPTS   16384
#define BATCH  2
#define HBEV   200
#define WBEV   176
#define CBEV   256
#define HW     (HBEV*WBEV)
#define KTOT   2048
#define NROWS  (BATCH*KTOT)
#define CMPN   8192
#define FULLM  0xffffffffu
#define TBLK   136          // transpose blocks fused alongside the 6 FPS blocks

// ---------------- static device scratch ----------------
__device__ float4 g_pts[BATCH*NPTS];             // SoA points: x,y,z,intensity
__device__ float4 g_cmp[6*CMPN];                 // per (batch,band) compacted pts, padded 1e15
__device__ int    g_cnt[6];                      // compacted counts
__device__ float  g_sfT[(size_t)BATCH*HW*CBEV];  // spatial features [b][hw][c]
__device__ float  g_kp[NROWS*3];                 // keypoint coords

// ---------------- packed f32x2 + redux helpers ----------------
__device__ __forceinline__ unsigned long long pk2(float lo, float hi) {
    unsigned long long r; asm("mov.b64 %0, {%1, %2};" : "=l"(r) : "f"(lo), "f"(hi)); return r;
}
__device__ __forceinline__ void upk2(unsigned long long v, float& lo, float& hi) {
    asm("mov.b64 {%0, %1}, %2;" : "=f"(lo), "=f"(hi) : "l"(v));
}
__device__ __forceinline__ unsigned long long addx2(unsigned long long a, unsigned long long b) {
    unsigned long long r; asm("add.rn.f32x2 %0, %1, %2;" : "=l"(r) : "l"(a), "l"(b)); return r;
}
__device__ __forceinline__ unsigned long long mulx2(unsigned long long a, unsigned long long b) {
    unsigned long long r; asm("mul.rn.f32x2 %0, %1, %2;" : "=l"(r) : "l"(a), "l"(b)); return r;
}
__device__ __forceinline__ unsigned redux_maxu(unsigned v) {
    unsigned r; asm("redux.sync.max.u32 %0, %1, 0xffffffff;" : "=r"(r) : "r"(v)); return r;
}
__device__ __forceinline__ unsigned redux_minu(unsigned v) {
    unsigned r; asm("redux.sync.min.u32 %0, %1, 0xffffffff;" : "=r"(r) : "r"(v)); return r;
}

// ---------------- compact bands (order-preserving) + build SoA points ----------------
__global__ void __launch_bounds__(1024) compact_kernel(const float* __restrict__ pts,
                                                       const float* __restrict__ rng) {
    int run = blockIdx.x, b = run/3, band = run - b*3;
    int t = threadIdx.x;
    const float* R = rng + (size_t)b*NPTS;
    int base = t*16;
    unsigned bits = 0; int cnt = 0;
    #pragma unroll
    for (int u = 0; u < 16; u++) {
        float r = R[base + u];
        bool sh = (r > 0.0f) && (r < 25.0f);
        bool lg = (r > 45.0f);
        bool v = (band == 0) ? sh : ((band == 2) ? lg : (!lg && !sh));
        if (v) { bits |= (1u << u); cnt++; }
    }
    __shared__ int wsum[32];
    __shared__ int s_tot;
    int lane = t & 31, warp = t >> 5;
    int inc = cnt;
    #pragma unroll
    for (int off = 1; off < 32; off <<= 1) {
        int o = __shfl_up_sync(FULLM, inc, off);
        if (lane >= off) inc += o;
    }
    if (lane == 31) wsum[warp] = inc;
    __syncthreads();
    if (warp == 0) {
        int v = wsum[lane];
        #pragma unroll
        for (int off = 1; off < 32; off <<= 1) {
            int o = __shfl_up_sync(FULLM, v, off);
            if (lane >= off) v += o;
        }
        wsum[lane] = v;
        if (lane == 31) s_tot = v;
    }
    __syncthreads();
    int off0 = inc - cnt + (warp ? wsum[warp-1] : 0);
    float4* dst = g_cmp + run*CMPN;
    #pragma unroll
    for (int u = 0; u < 16; u++) {
        if ((bits >> u) & 1u) {
            if (off0 < CMPN) {
                const float* p = pts + (size_t)(b*NPTS + base + u)*5;
                dst[off0] = make_float4(p[1], p[2], p[3], p[4]);
            }
            off0++;
        }
    }
    if (t == 0) g_cnt[run] = s_tot;
    for (int i = s_tot + t; i < CMPN; i += 1024)
        dst[i] = make_float4(1e15f, 1e15f, 1e15f, 0.f);
    // build SoA float4 points (used by sa_kernel)
    for (int i = run*1024 + t; i < BATCH*NPTS; i += 6*1024) {
        const float* p = pts + (size_t)i*5;
        g_pts[i] = make_float4(p[1], p[2], p[3], p[4]);
    }
}

// ---------------- fused: FPS (blocks 0..5) + BEV transpose (blocks 6..) ----------------
__global__ void __launch_bounds__(1024,1) fused_kernel(const float* __restrict__ sf,
                                                       float* __restrict__ coords_out) {
    __shared__ unsigned sv[2][32];
    __shared__ unsigned si[2][32];
    __shared__ float tile[32][33];

    int t = threadIdx.x;
    if (blockIdx.x >= 6) {
        // ---- transpose [b][c][hw] -> [b][hw][c], runs concurrently with FPS ----
        int tx = t & 31, ty = t >> 5;
        const int NT = 2*(CBEV/32)*(HW/32);   // 2*8*1100
        for (int tid0 = (int)blockIdx.x - 6; tid0 < NT; tid0 += TBLK) {
            int b   = tid0 / ((CBEV/32)*(HW/32));
            int rem = tid0 - b*((CBEV/32)*(HW/32));
            int cg  = rem / (HW/32), hg = rem - cg*(HW/32);
            int c0 = cg*32, hw0 = hg*32;
            const float* src = sf   + (size_t)b*CBEV*HW;
            float*       dst = g_sfT + (size_t)b*HW*CBEV;
            __syncthreads();     // protect tile reuse (WAR)
            tile[ty][tx] = src[(size_t)(c0+ty)*HW + hw0 + tx];
            __syncthreads();
            dst[(size_t)(hw0+ty)*CBEV + c0 + tx] = tile[tx][ty];
        }
        return;
    }

    // ---- furthest point sampling: register-resident, 1 barrier/iter ----
    int run = blockIdx.x, b = run/3, band = run - b*3;
    int K = (band == 0) ? 1024 : 512;
    int kpbase = b*KTOT + (band==0 ? 0 : (band==1 ? 1024 : 1536));
    int lane = t & 31, warp = t >> 5;
    const float4* cm = g_cmp + run*CMPN;
    int M = g_cnt[run];
    int jmax = min(8, (M + 1023) >> 10);
    int pmax = (jmax + 1) >> 1;

    unsigned long long X2[4], Y2[4], Z2[4];
    float D[8];
    #pragma unroll
    for (int p = 0; p < 4; p++) {
        float4 a = cm[(2*p)*1024 + t];
        float4 c = cm[(2*p+1)*1024 + t];
        X2[p] = pk2(a.x, c.x); Y2[p] = pk2(a.y, c.y); Z2[p] = pk2(a.z, c.z);
        D[2*p]   = ((2*p)*1024 + t   < M) ? 1e10f : -1.0f;
        D[2*p+1] = ((2*p+1)*1024 + t < M) ? 1e10f : -1.0f;
    }

    int sel = 0;   // first valid point = compacted index 0
    for (int k = 0; ; k++) {
        float4 w = __ldg(cm + sel);      // uniform broadcast load (L1-resident)
        if (t == 0) {
            int r = kpbase + k;
            g_kp[r*3+0] = w.x; g_kp[r*3+1] = w.y; g_kp[r*3+2] = w.z;
            coords_out[r*4+0] = (float)b;
            coords_out[r*4+1] = w.x; coords_out[r*4+2] = w.y; coords_out[r*4+3] = w.z;
        }
        if (k == K-1) break;

        unsigned long long nx = pk2(-w.x, -w.x);
        unsigned long long ny = pk2(-w.y, -w.y);
        unsigned long long nz = pk2(-w.z, -w.z);
        float best = -1.0f;
        #pragma unroll 4
        for (int p = 0; p < pmax; p++) {
            unsigned long long dx = addx2(X2[p], nx);
            unsigned long long dy = addx2(Y2[p], ny);
            unsigned long long dz = addx2(Z2[p], nz);
            // ((dx*dx + dy*dy) + dz*dz) in rn — bit-exact vs scalar reference
            unsigned long long d2 = addx2(addx2(mulx2(dx,dx), mulx2(dy,dy)), mulx2(dz,dz));
            float dl, dh; upk2(d2, dl, dh);
            float n0 = fminf(D[2*p],   dl); D[2*p]   = n0;
            float n1 = fminf(D[2*p+1], dh); D[2*p+1] = n1;
            best = fmaxf(best, fmaxf(n0, n1));
        }
        best = fmaxf(best, 0.0f);
        unsigned myidx = 0x7fffffffu;
        #pragma unroll
        for (int j = 7; j >= 0; j--)
            if (D[j] == best) myidx = (unsigned)(j*1024 + t);   // smallest j wins

        unsigned u  = __float_as_uint(best);          // d>=0 => bits order-isomorphic
        unsigned vm = redux_maxu(u);
        unsigned cand = (u == vm) ? myidx : 0x7fffffffu;
        unsigned im = redux_minu(cand);
        int par = k & 1;
        if (lane == 0) { sv[par][warp] = vm; si[par][warp] = im; }
        __syncthreads();
        unsigned v2 = sv[par][lane];
        unsigned i2 = si[par][lane];
        unsigned g  = redux_maxu(v2);
        unsigned c2 = (v2 == g) ? i2 : 0x7fffffffu;
        sel = (int)redux_minu(c2);                    // all warps agree
    }
}

// ---------------- BEV bilinear gather ----------------
__global__ void bev_kernel(float* __restrict__ outFeats) {
    int row = blockIdx.x;
    int b = row >> 11;
    float kx = g_kp[row*3+0], ky = g_kp[row*3+1];
    float xi = ((kx - 0.0f)     / 0.05f) / 8.0f;
    float yi = ((ky - (-40.0f)) / 0.05f) / 8.0f;
    int x0 = (int)floorf(xi); int x1 = x0 + 1;
    int y0 = (int)floorf(yi); int y1 = y0 + 1;
    x0 = min(max(x0, 0), WBEV-1); x1 = min(max(x1, 0), WBEV-1);
    y0 = min(max(y0, 0), HBEV-1); y1 = min(max(y1, 0), HBEV-1);
    float x0f = (float)x0, x1f = (float)x1, y0f = (float)y0, y1f = (float)y1;
    float wa = (x1f - xi)*(y1f - yi);
    float wb = (x1f - xi)*(yi - y0f);
    float wc = (xi - x0f)*(y1f - yi);
    float wd = (xi - x0f)*(yi - y0f);
    const float* bb = g_sfT + (size_t)b*HW*CBEV;
    const float* Ia = bb + (size_t)(y0*WBEV + x0)*CBEV;
    const float* Ib = bb + (size_t)(y1*WBEV + x0)*CBEV;
    const float* Ic = bb + (size_t)(y0*WBEV + x1)*CBEV;
    const float* Id = bb + (size_t)(y1*WBEV + x1)*CBEV;
    int c = threadIdx.x;
    outFeats[(size_t)row*288 + c] = Ia[c]*wa + Ib[c]*wb + Ic[c]*wc + Id[c]*wd;
}

// ---------------- ball query via smem point tiles + MLP + maxpool ----------------
__global__ void __launch_bounds__(512) sa_kernel(
        const float* __restrict__ w0, const float* __restrict__ bn0,
        const float* __restrict__ w1, const float* __restrict__ bn1,
        float* __restrict__ outFeats) {
    __shared__ float4 spts[2048];
    __shared__ float sw0[128];
    __shared__ float sw1[512];
    __shared__ float sb0s[32], sb0m[32], sb0b[32];
    __shared__ float sb1s[32], sb1m[32], sb1b[32];
    __shared__ int   sidx[16][2][16];
    int tid = threadIdx.x;
    if (tid < 128) sw0[tid] = w0[tid];
    sw1[tid] = w1[tid];
    if (tid < 32) {
        int br = tid >> 4, c = tid & 15;
        float g = bn0[br*64 + c], be = bn0[br*64+16+c], m = bn0[br*64+32+c], v = bn0[br*64+48+c];
        sb0s[tid] = g * (1.0f/sqrtf(v + 1e-5f)); sb0m[tid] = m; sb0b[tid] = be;
        g = bn1[br*64 + c]; be = bn1[br*64+16+c]; m = bn1[br*64+32+c]; v = bn1[br*64+48+c];
        sb1s[tid] = g * (1.0f/sqrtf(v + 1e-5f)); sb1m[tid] = m; sb1b[tid] = be;
    }

    int w = tid >> 5, lane = tid & 31;
    int row = blockIdx.x*16 + w;
    int b = row >> 11;
    float kx = g_kp[row*3], ky = g_kp[row*3+1], kz = g_kp[row*3+2];
    const float4* P = g_pts + (size_t)b*NPTS;
    unsigned lt = (1u << lane) - 1u;

    int c1 = 0, c2 = 0;
    for (int base0 = 0; base0 < NPTS; base0 += 2048) {
        __syncthreads();                        // WAR: prior scan done before reload
        #pragma unroll
        for (int i = 0; i < 4; i++) spts[tid + i*512] = P[base0 + tid + i*512];
        __syncthreads();
        if (c1 < 16 || c2 < 16) {
            for (int off = 0; off < 2048; off += 32) {
                float4 p = spts[off + lane];
                float dx = kx - p.x, dy = ky - p.y, dz = kz - p.z;
                float d2 = __fadd_rn(__fadd_rn(__fmul_rn(dx,dx), __fmul_rn(dy,dy)), __fmul_rn(dz,dz));
                bool v1 = d2 < 1.0f, v2 = d2 < 4.0f;
                unsigned m1 = __ballot_sync(FULLM, v1);
                unsigned m2 = __ballot_sync(FULLM, v2);
                if (c1 < 16 && m1) {
                    int rk = __popc(m1 & lt);
                    if (v1 && c1 + rk < 16) sidx[w][0][c1+rk] = base0 + off + lane;
                    c1 = min(c1 + __popc(m1), 16);
                }
                if (c2 < 16 && m2) {
                    int rk = __popc(m2 & lt);
                    if (v2 && c2 + rk < 16) sidx[w][1][c2+rk] = base0 + off + lane;
                    c2 = min(c2 + __popc(m2), 16);
                }
                if (c1 >= 16 && c2 >= 16) break;
            }
        }
    }
    __syncwarp();

    int rI = lane >> 4, s = lane & 15;
    int cnt = rI ? c2 : c1;
    float gx = 0.f, gy = 0.f, gz = 0.f, gi = 0.f;
    if (cnt > 0) {
        int id = sidx[w][rI][(s < cnt) ? s : 0];
        float4 p = P[id];
        gx = p.x - kx; gy = p.y - ky; gz = p.z - kz; gi = p.w;
    }
    const float* W0  = sw0  + rI*64;
    const float* W1  = sw1  + rI*256;
    const float* B0s = sb0s + rI*16; const float* B0m = sb0m + rI*16; const float* B0b = sb0b + rI*16;
    const float* B1s = sb1s + rI*16; const float* B1m = sb1m + rI*16; const float* B1b = sb1b + rI*16;

    float h1[16];
    #pragma unroll
    for (int c = 0; c < 16; c++) {
        float a = gx*W0[c] + gy*W0[16+c] + gz*W0[32+c] + gi*W0[48+c];
        h1[c] = fmaxf((a - B0m[c])*B0s[c] + B0b[c], 0.0f);
    }
    float h2[16];
    #pragma unroll
    for (int c = 0; c < 16; c++) {
        float a = 0.f;
        #pragma unroll
        for (int k = 0; k < 16; k++) a += h1[k]*W1[k*16 + c];
        h2[c] = fmaxf((a - B1m[c])*B1s[c] + B1b[c], 0.0f);
    }
    #pragma unroll
    for (int off = 8; off; off >>= 1) {
        #pragma unroll
        for (int c = 0; c < 16; c++)
            h2[c] = fmaxf(h2[c], __shfl_xor_sync(FULLM, h2[c], off));
    }
    if (s == 0) {
        float* o = outFeats + (size_t)row*288 + 256 + rI*16;
        #pragma unroll
        for (int c = 0; c < 16; c++) o[c] = h2[c];
    }
}

// ---------------- fusion: [4096,288] @ [288,128] + BN + ReLU ----------------
__global__ void __launch_bounds__(128) fusion_kernel(
        const float* __restrict__ feats, const float* __restrict__ fw,
        const float* __restrict__ fbn, float* __restrict__ out) {
    __shared__ float sr[16*288];
    int tid = threadIdx.x;
    size_t row0 = (size_t)blockIdx.x * 16;
    for (int i = tid; i < 16*288; i += 128) sr[i] = feats[row0*288 + i];
    __syncthreads();
    float acc[16];
    #pragma unroll
    for (int r = 0; r < 16; r++) acc[r] = 0.f;
    for (int k = 0; k < 288; k++) {
        float wv = fw[(size_t)k*128 + tid];
        #pragma unroll
        for (int r = 0; r < 16; r++) acc[r] += sr[r*288 + k] * wv;
    }
    float g = fbn[tid], be = fbn[128+tid], m = fbn[256+tid], v = fbn[384+tid];
    float sc = g * (1.0f/sqrtf(v + 1e-5f));
    #pragma unroll
    for (int r = 0; r < 16; r++)
        out[(row0 + r)*128 + tid] = fmaxf((acc[r] - m)*sc + be, 0.f);
}

// ---------------- launch ----------------
extern "C" void kernel_launch(void* const* d_in, const int* in_sizes, int n_in,
                              void* d_out, int out_size) {
    const float* points = (const float*)d_in[0];
    const float* rng    = (const float*)d_in[1];
    const float* sf     = (const float*)d_in[2];
    const float* sa_w0  = (const float*)d_in[3];
    const float* sa_bn0 = (const float*)d_in[4];
    const float* sa_w1  = (const float*)d_in[5];
    const float* sa_bn1 = (const float*)d_in[6];
    const float* fw     = (const float*)d_in[7];
    const float* fbn    = (const float*)d_in[8];
    float* out = (float*)d_out;

    float* fused  = out;                                          // [4096,128]
    float* feats  = out + (size_t)NROWS*128;                      // [4096,288]
    float* coords = out + (size_t)NROWS*128 + (size_t)NROWS*288;  // [4096,4]

    compact_kernel<<<6, 1024>>>(points, rng);
    fused_kernel<<<6 + TBLK, 1024>>>(sf, coords);
    bev_kernel<<<NROWS, 256>>>(feats);
    sa_kernel<<<NROWS/16, 512>>>(sa_w0, sa_bn0, sa_w1, sa_bn1, feats);
    fusion_kernel<<<NROWS/16, 128>>>(feats, fw, fbn, fused);
}

// round 3
// speedup vs baseline: 2.5482x; 2.2385x over previous
#include <cuda_runtime.h>
#include <math.h>

#define NPTS   16384
#define BATCH  2
#define HBEV   200
#define WBEV   176
#define CBEV   256
#define HW     (HBEV*WBEV)
#define KTOT   2048
#define NROWS  (BATCH*KTOT)
#define CMPN   8192
#define FULLM  0xffffffffu

// ---------------- static device scratch ----------------
__device__ float4 g_pts[BATCH*NPTS];       // SoA points: x,y,z,intensity
__device__ float4 g_cmp[6*CMPN];           // per (batch,band) compacted pts, padded 1e15
__device__ int    g_cnt[6];                // compacted counts
__device__ float  g_kp[NROWS*3];           // keypoint coords
__device__ int    g_ballidx[NROWS*32];     // [row][2][16] neighbor indices
__device__ int    g_ballcnt[NROWS*2];      // [row][2] capped counts

// ---------------- packed f32x2 + redux helpers ----------------
__device__ __forceinline__ unsigned long long pk2(float lo, float hi) {
    unsigned long long r; asm("mov.b64 %0, {%1, %2};" : "=l"(r) : "f"(lo), "f"(hi)); return r;
}
__device__ __forceinline__ void upk2(unsigned long long v, float& lo, float& hi) {
    asm("mov.b64 {%0, %1}, %2;" : "=f"(lo), "=f"(hi) : "l"(v));
}
__device__ __forceinline__ unsigned long long addx2(unsigned long long a, unsigned long long b) {
    unsigned long long r; asm("add.rn.f32x2 %0, %1, %2;" : "=l"(r) : "l"(a), "l"(b)); return r;
}
__device__ __forceinline__ unsigned long long mulx2(unsigned long long a, unsigned long long b) {
    unsigned long long r; asm("mul.rn.f32x2 %0, %1, %2;" : "=l"(r) : "l"(a), "l"(b)); return r;
}
__device__ __forceinline__ unsigned redux_maxu(unsigned v) {
    unsigned r; asm("redux.sync.max.u32 %0, %1, 0xffffffff;" : "=r"(r) : "r"(v)); return r;
}
__device__ __forceinline__ unsigned redux_minu(unsigned v) {
    unsigned r; asm("redux.sync.min.u32 %0, %1, 0xffffffff;" : "=r"(r) : "r"(v)); return r;
}

// ---------------- compact bands (order-preserving) + build SoA points ----------------
__global__ void __launch_bounds__(1024) compact_kernel(const float* __restrict__ pts,
                                                       const float* __restrict__ rng) {
    int run = blockIdx.x, b = run/3, band = run - b*3;
    int t = threadIdx.x;
    const float* R = rng + (size_t)b*NPTS;
    int base = t*16;
    unsigned bits = 0; int cnt = 0;
    #pragma unroll
    for (int u = 0; u < 16; u++) {
        float r = R[base + u];
        bool sh = (r > 0.0f) && (r < 25.0f);
        bool lg = (r > 45.0f);
        bool v = (band == 0) ? sh : ((band == 2) ? lg : (!lg && !sh));
        if (v) { bits |= (1u << u); cnt++; }
    }
    __shared__ int wsum[32];
    __shared__ int s_tot;
    int lane = t & 31, warp = t >> 5;
    int inc = cnt;
    #pragma unroll
    for (int off = 1; off < 32; off <<= 1) {
        int o = __shfl_up_sync(FULLM, inc, off);
        if (lane >= off) inc += o;
    }
    if (lane == 31) wsum[warp] = inc;
    __syncthreads();
    if (warp == 0) {
        int v = wsum[lane];
        #pragma unroll
        for (int off = 1; off < 32; off <<= 1) {
            int o = __shfl_up_sync(FULLM, v, off);
            if (lane >= off) v += o;
        }
        wsum[lane] = v;
        if (lane == 31) s_tot = v;
    }
    __syncthreads();
    int off0 = inc - cnt + (warp ? wsum[warp-1] : 0);
    float4* dst = g_cmp + run*CMPN;
    #pragma unroll
    for (int u = 0; u < 16; u++) {
        if ((bits >> u) & 1u) {
            if (off0 < CMPN) {
                const float* p = pts + (size_t)(b*NPTS + base + u)*5;
                dst[off0] = make_float4(p[1], p[2], p[3], p[4]);
            }
            off0++;
        }
    }
    if (t == 0) g_cnt[run] = s_tot;
    for (int i = s_tot + t; i < CMPN; i += 1024)
        dst[i] = make_float4(1e15f, 1e15f, 1e15f, 0.f);
    for (int i = run*1024 + t; i < BATCH*NPTS; i += 6*1024) {
        const float* p = pts + (size_t)i*5;
        g_pts[i] = make_float4(p[1], p[2], p[3], p[4]);
    }
}

// ---------------- FPS body, sized to the actual band population ----------------
template<int PMAX>
__device__ __forceinline__ void fps_run(int b, int K, int kpbase, const float4* __restrict__ cm,
                                        int M, float* __restrict__ coords_out,
                                        unsigned (*sv)[32], unsigned (*si)[32]) {
    int t = threadIdx.x;
    int lane = t & 31, warp = t >> 5;
    unsigned long long X2[PMAX], Y2[PMAX], Z2[PMAX];
    float D[2*PMAX];
    #pragma unroll
    for (int p = 0; p < PMAX; p++) {
        float4 a = cm[(2*p)*1024 + t];
        float4 c = cm[(2*p+1)*1024 + t];
        X2[p] = pk2(a.x, c.x); Y2[p] = pk2(a.y, c.y); Z2[p] = pk2(a.z, c.z);
        D[2*p]   = ((2*p)*1024 + t   < M) ? 1e10f : -1.0f;
        D[2*p+1] = ((2*p+1)*1024 + t < M) ? 1e10f : -1.0f;
    }

    int sel = 0;
    for (int k = 0; ; k++) {
        float4 w = __ldg(cm + sel);
        if (t == 0) {
            int r = kpbase + k;
            g_kp[r*3+0] = w.x; g_kp[r*3+1] = w.y; g_kp[r*3+2] = w.z;
            coords_out[r*4+0] = (float)b;
            coords_out[r*4+1] = w.x; coords_out[r*4+2] = w.y; coords_out[r*4+3] = w.z;
        }
        if (k == K-1) break;

        unsigned long long nx = pk2(-w.x, -w.x);
        unsigned long long ny = pk2(-w.y, -w.y);
        unsigned long long nz = pk2(-w.z, -w.z);
        float best = -1.0f;
        #pragma unroll
        for (int p = 0; p < PMAX; p++) {
            unsigned long long dx = addx2(X2[p], nx);
            unsigned long long dy = addx2(Y2[p], ny);
            unsigned long long dz = addx2(Z2[p], nz);
            unsigned long long d2 = addx2(addx2(mulx2(dx,dx), mulx2(dy,dy)), mulx2(dz,dz));
            float dl, dh; upk2(d2, dl, dh);
            float n0 = fminf(D[2*p],   dl); D[2*p]   = n0;
            float n1 = fminf(D[2*p+1], dh); D[2*p+1] = n1;
            best = fmaxf(best, fmaxf(n0, n1));
        }
        best = fmaxf(best, 0.0f);
        unsigned myidx = 0x7fffffffu;
        #pragma unroll
        for (int j = 2*PMAX-1; j >= 0; j--)
            if (D[j] == best) myidx = (unsigned)(j*1024 + t);

        unsigned u  = __float_as_uint(best);
        unsigned vm = redux_maxu(u);
        unsigned cand = (u == vm) ? myidx : 0x7fffffffu;
        unsigned im = redux_minu(cand);
        int par = k & 1;
        if (lane == 0) { sv[par][warp] = vm; si[par][warp] = im; }
        __syncthreads();
        unsigned v2 = sv[par][lane];
        unsigned i2 = si[par][lane];
        unsigned g  = redux_maxu(v2);
        unsigned c2 = (v2 == g) ? i2 : 0x7fffffffu;
        sel = (int)redux_minu(c2);
    }
}

__global__ void __launch_bounds__(1024,1) fps_kernel(float* __restrict__ coords_out) {
    __shared__ unsigned sv[2][32];
    __shared__ unsigned si[2][32];
    int run = blockIdx.x, b = run/3, band = run - b*3;
    int K = (band == 0) ? 1024 : 512;
    int kpbase = b*KTOT + (band==0 ? 0 : (band==1 ? 1024 : 1536));
    const float4* cm = g_cmp + run*CMPN;
    int M = g_cnt[run];
    int pmax = min(4, (M + 2047) >> 11);
    switch (pmax) {
        case 1: fps_run<1>(b, K, kpbase, cm, M, coords_out, sv, si); break;
        case 2: fps_run<2>(b, K, kpbase, cm, M, coords_out, sv, si); break;
        case 3: fps_run<3>(b, K, kpbase, cm, M, coords_out, sv, si); break;
        default: fps_run<4>(b, K, kpbase, cm, M, coords_out, sv, si); break;
    }
}

// ---------------- BEV bilinear: direct CHW gather, no transpose ----------------
__global__ void __launch_bounds__(256) bev_kernel(const float* __restrict__ sf,
                                                  float* __restrict__ outFeats) {
    int row = blockIdx.x;
    int b = row >> 11;
    float kx = g_kp[row*3+0], ky = g_kp[row*3+1];
    float xi = ((kx - 0.0f)     / 0.05f) / 8.0f;
    float yi = ((ky - (-40.0f)) / 0.05f) / 8.0f;
    int x0 = (int)floorf(xi); int x1 = x0 + 1;
    int y0 = (int)floorf(yi); int y1 = y0 + 1;
    x0 = min(max(x0, 0), WBEV-1); x1 = min(max(x1, 0), WBEV-1);
    y0 = min(max(y0, 0), HBEV-1); y1 = min(max(y1, 0), HBEV-1);
    float x0f = (float)x0, x1f = (float)x1, y0f = (float)y0, y1f = (float)y1;
    float wa = (x1f - xi)*(y1f - yi);
    float wb = (x1f - xi)*(yi - y0f);
    float wc = (xi - x0f)*(y1f - yi);
    float wd = (xi - x0f)*(yi - y0f);
    int c = threadIdx.x;
    const float* ch = sf + ((size_t)b*CBEV + c)*HW;
    float Ia = __ldg(ch + y0*WBEV + x0);
    float Ib = __ldg(ch + y1*WBEV + x0);
    float Ic = __ldg(ch + y0*WBEV + x1);
    float Id = __ldg(ch + y1*WBEV + x1);
    outFeats[(size_t)row*288 + c] = Ia*wa + Ib*wb + Ic*wc + Id*wd;
}

// ---------------- ball-query scan: gated bookkeeping, 2 pts/lane ----------------
__global__ void __launch_bounds__(512) sa_scan_kernel() {
    __shared__ float4 spts[2048];
    __shared__ int   sidx[16][2][16];
    int tid = threadIdx.x;
    int w = tid >> 5, lane = tid & 31;
    int row = blockIdx.x*16 + w;
    int b = row >> 11;
    float kx = g_kp[row*3], ky = g_kp[row*3+1], kz = g_kp[row*3+2];
    unsigned long long nkx = pk2(-kx, -kx), nky = pk2(-ky, -ky), nkz = pk2(-kz, -kz);
    const float4* P = g_pts + (size_t)b*NPTS;
    unsigned lt  = (1u << lane) - 1u;
    unsigned lte = lt | (1u << lane);

    int c1 = 0, c2 = 0;
    for (int base0 = 0; base0 < NPTS; base0 += 2048) {
        __syncthreads();
        #pragma unroll
        for (int i = 0; i < 4; i++) spts[tid + i*512] = P[base0 + tid + i*512];
        __syncthreads();
        if (c1 >= 16 && c2 >= 16) continue;
        for (int off = 0; off < 2048; off += 64) {
            float4 p0 = spts[off + 2*lane];
            float4 p1 = spts[off + 2*lane + 1];
            unsigned long long dx = addx2(pk2(p0.x, p1.x), nkx);
            unsigned long long dy = addx2(pk2(p0.y, p1.y), nky);
            unsigned long long dz = addx2(pk2(p0.z, p1.z), nkz);
            unsigned long long d2 = addx2(addx2(mulx2(dx,dx), mulx2(dy,dy)), mulx2(dz,dz));
            float da, db; upk2(d2, da, db);
            bool v2a = da < 4.0f, v2b = db < 4.0f;
            if (__ballot_sync(FULLM, v2a || v2b)) {
                bool v1a = da < 1.0f, v1b = db < 1.0f;
                unsigned m1e = __ballot_sync(FULLM, v1a);
                unsigned m1o = __ballot_sync(FULLM, v1b);
                unsigned m2e = __ballot_sync(FULLM, v2a);
                unsigned m2o = __ballot_sync(FULLM, v2b);
                int gi = base0 + off + 2*lane;
                if (c1 < 16 && (m1e | m1o)) {
                    int re = __popc(m1e & lt)  + __popc(m1o & lt);
                    int ro = __popc(m1e & lte) + __popc(m1o & lt);
                    if (v1a && c1 + re < 16) sidx[w][0][c1+re] = gi;
                    if (v1b && c1 + ro < 16) sidx[w][0][c1+ro] = gi + 1;
                    c1 = min(c1 + __popc(m1e) + __popc(m1o), 16);
                }
                if (c2 < 16) {
                    int re = __popc(m2e & lt)  + __popc(m2o & lt);
                    int ro = __popc(m2e & lte) + __popc(m2o & lt);
                    if (v2a && c2 + re < 16) sidx[w][1][c2+re] = gi;
                    if (v2b && c2 + ro < 16) sidx[w][1][c2+ro] = gi + 1;
                    c2 = min(c2 + __popc(m2e) + __popc(m2o), 16);
                }
                if (c1 >= 16 && c2 >= 16) break;
            }
        }
    }
    __syncwarp();
    // dump to global
    if (lane < 2) g_ballcnt[row*2 + lane] = lane ? c2 : c1;
    int rI = lane >> 4, s = lane & 15;
    int cnt = rI ? c2 : c1;
    g_ballidx[row*32 + lane] = (s < cnt) ? sidx[w][rI][s] : (cnt > 0 ? sidx[w][rI][0] : 0);
}

// ---------------- MLP + maxpool over gathered neighbors ----------------
__global__ void __launch_bounds__(256) sa_mlp_kernel(
        const float* __restrict__ w0, const float* __restrict__ bn0,
        const float* __restrict__ w1, const float* __restrict__ bn1,
        float* __restrict__ outFeats) {
    __shared__ float sw0[128];
    __shared__ float sw1[512];
    __shared__ float sb0s[32], sb0m[32], sb0b[32];
    __shared__ float sb1s[32], sb1m[32], sb1b[32];
    int tid = threadIdx.x;
    if (tid < 128) sw0[tid] = w0[tid];
    for (int i = tid; i < 512; i += 256) sw1[i] = w1[i];
    if (tid < 32) {
        int br = tid >> 4, c = tid & 15;
        float g = bn0[br*64 + c], be = bn0[br*64+16+c], m = bn0[br*64+32+c], v = bn0[br*64+48+c];
        sb0s[tid] = g * (1.0f/sqrtf(v + 1e-5f)); sb0m[tid] = m; sb0b[tid] = be;
        g = bn1[br*64 + c]; be = bn1[br*64+16+c]; m = bn1[br*64+32+c]; v = bn1[br*64+48+c];
        sb1s[tid] = g * (1.0f/sqrtf(v + 1e-5f)); sb1m[tid] = m; sb1b[tid] = be;
    }
    __syncthreads();

    int w = tid >> 5, lane = tid & 31;
    int row = blockIdx.x*8 + w;
    int b = row >> 11;
    float kx = g_kp[row*3], ky = g_kp[row*3+1], kz = g_kp[row*3+2];
    const float4* P = g_pts + (size_t)b*NPTS;

    int rI = lane >> 4, s = lane & 15;
    int cnt = g_ballcnt[row*2 + rI];
    float gx = 0.f, gy = 0.f, gz = 0.f, gi = 0.f;
    if (cnt > 0) {
        int id = g_ballidx[row*32 + rI*16 + ((s < cnt) ? s : 0)];
        float4 p = P[id];
        gx = p.x - kx; gy = p.y - ky; gz = p.z - kz; gi = p.w;
    }
    const float* W0  = sw0  + rI*64;
    const float* W1  = sw1  + rI*256;
    const float* B0s = sb0s + rI*16; const float* B0m = sb0m + rI*16; const float* B0b = sb0b + rI*16;
    const float* B1s = sb1s + rI*16; const float* B1m = sb1m + rI*16; const float* B1b = sb1b + rI*16;

    float h1[16];
    #pragma unroll
    for (int c = 0; c < 16; c++) {
        float a = gx*W0[c] + gy*W0[16+c] + gz*W0[32+c] + gi*W0[48+c];
        h1[c] = fmaxf((a - B0m[c])*B0s[c] + B0b[c], 0.0f);
    }
    float h2[16];
    #pragma unroll
    for (int c = 0; c < 16; c++) {
        float a = 0.f;
        #pragma unroll
        for (int k = 0; k < 16; k++) a += h1[k]*W1[k*16 + c];
        h2[c] = fmaxf((a - B1m[c])*B1s[c] + B1b[c], 0.0f);
    }
    #pragma unroll
    for (int off = 8; off; off >>= 1) {
        #pragma unroll
        for (int c = 0; c < 16; c++)
            h2[c] = fmaxf(h2[c], __shfl_xor_sync(FULLM, h2[c], off));
    }
    if (s == 0) {
        float* o = outFeats + (size_t)row*288 + 256 + rI*16;
        #pragma unroll
        for (int c = 0; c < 16; c++) o[c] = h2[c];
    }
}

// ---------------- fusion: [4096,288] @ [288,128] + BN + ReLU ----------------
__global__ void __launch_bounds__(128) fusion_kernel(
        const float* __restrict__ feats, const float* __restrict__ fw,
        const float* __restrict__ fbn, float* __restrict__ out) {
    __shared__ float sr[16*288];
    int tid = threadIdx.x;
    size_t row0 = (size_t)blockIdx.x * 16;
    for (int i = tid; i < 16*288; i += 128) sr[i] = feats[row0*288 + i];
    __syncthreads();
    float acc[16];
    #pragma unroll
    for (int r = 0; r < 16; r++) acc[r] = 0.f;
    for (int k = 0; k < 288; k++) {
        float wv = __ldg(fw + (size_t)k*128 + tid);
        #pragma unroll
        for (int r = 0; r < 16; r++) acc[r] += sr[r*288 + k] * wv;
    }
    float g = fbn[tid], be = fbn[128+tid], m = fbn[256+tid], v = fbn[384+tid];
    float sc = g * (1.0f/sqrtf(v + 1e-5f));
    #pragma unroll
    for (int r = 0; r < 16; r++)
        out[(row0 + r)*128 + tid] = fmaxf((acc[r] - m)*sc + be, 0.f);
}

// ---------------- launch ----------------
extern "C" void kernel_launch(void* const* d_in, const int* in_sizes, int n_in,
                              void* d_out, int out_size) {
    const float* points = (const float*)d_in[0];
    const float* rng    = (const float*)d_in[1];
    const float* sf     = (const float*)d_in[2];
    const float* sa_w0  = (const float*)d_in[3];
    const float* sa_bn0 = (const float*)d_in[4];
    const float* sa_w1  = (const float*)d_in[5];
    const float* sa_bn1 = (const float*)d_in[6];
    const float* fw     = (const float*)d_in[7];
    const float* fbn    = (const float*)d_in[8];
    float* out = (float*)d_out;

    float* fused  = out;                                          // [4096,128]
    float* feats  = out + (size_t)NROWS*128;                      // [4096,288]
    float* coords = out + (size_t)NROWS*128 + (size_t)NROWS*288;  // [4096,4]

    compact_kernel<<<6, 1024>>>(points, rng);
    fps_kernel<<<6, 1024>>>(coords);
    bev_kernel<<<NROWS, 256>>>(sf, feats);
    sa_scan_kernel<<<NROWS/16, 512>>>();
    sa_mlp_kernel<<<NROWS/8, 256>>>(sa_w0, sa_bn0, sa_w1, sa_bn1, feats);
    fusion_kernel<<<NROWS/16, 128>>>(feats, fw, fbn, fused);
}

// round 4
// speedup vs baseline: 3.1418x; 1.2329x over previous
#include <cuda_runtime.h>
#include <math.h>

#define NPTS   16384
#define BATCH  2
#define HBEV   200
#define WBEV   176
#define CBEV   256
#define HW     (HBEV*WBEV)
#define KTOT   2048
#define NROWS  (BATCH*KTOT)
#define CMPN   8192
#define FULLM  0xffffffffu
#define SCANB  256

// ---------------- static device scratch ----------------
__device__ float4 g_pts[BATCH*NPTS];       // SoA points: x,y,z,intensity
__device__ float  g_kp[NROWS*3];           // keypoint coords
__device__ int    g_ballidx[NROWS*32];     // [row][2][16] neighbor indices
__device__ int    g_ballcnt[NROWS*2];      // [row][2] capped counts

// ---------------- packed f32x2 + redux helpers ----------------
__device__ __forceinline__ unsigned long long pk2(float lo, float hi) {
    unsigned long long r; asm("mov.b64 %0, {%1, %2};" : "=l"(r) : "f"(lo), "f"(hi)); return r;
}
__device__ __forceinline__ void upk2(unsigned long long v, float& lo, float& hi) {
    asm("mov.b64 {%0, %1}, %2;" : "=f"(lo), "=f"(hi) : "l"(v));
}
__device__ __forceinline__ unsigned long long addx2(unsigned long long a, unsigned long long b) {
    unsigned long long r; asm("add.rn.f32x2 %0, %1, %2;" : "=l"(r) : "l"(a), "l"(b)); return r;
}
__device__ __forceinline__ unsigned long long mulx2(unsigned long long a, unsigned long long b) {
    unsigned long long r; asm("mul.rn.f32x2 %0, %1, %2;" : "=l"(r) : "l"(a), "l"(b)); return r;
}
__device__ __forceinline__ unsigned redux_maxu(unsigned v) {
    unsigned r; asm("redux.sync.max.u32 %0, %1, 0xffffffff;" : "=r"(r) : "r"(v)); return r;
}
__device__ __forceinline__ unsigned redux_minu(unsigned v) {
    unsigned r; asm("redux.sync.min.u32 %0, %1, 0xffffffff;" : "=r"(r) : "r"(v)); return r;
}

// ==================================================================
// FPS: compaction + furthest-point sampling fused, one block per band.
// 256 threads, band points register-resident (2 per slot via f32x2),
// compacted copy kept in 128KB dynamic smem for winner broadcast.
// ==================================================================
template<int P>
__device__ __forceinline__ void fps_body(int b, int K, int kpbase, int M,
                                         float* __restrict__ coords_out,
                                         unsigned (*sv)[8], unsigned (*si)[8]) {
    extern __shared__ float4 scmp[];
    int t = threadIdx.x;
    int lane = t & 31, warp = t >> 5;

    unsigned long long Xn[P], Yn[P], Zn[P];   // negated coords
    float D[2*P];
    #pragma unroll
    for (int p = 0; p < P; p++) {
        float4 a = scmp[(2*p)*256 + t];
        float4 c = scmp[(2*p+1)*256 + t];
        Xn[p] = pk2(-a.x, -c.x); Yn[p] = pk2(-a.y, -c.y); Zn[p] = pk2(-a.z, -c.z);
        D[2*p]   = ((2*p)*256 + t   < M) ? 1e10f : -1.0f;
        D[2*p+1] = ((2*p+1)*256 + t < M) ? 1e10f : -1.0f;
    }

    int sel = 0;   // first valid point = compacted index 0
    for (int k = 0; ; k++) {
        float4 w = scmp[sel];                // LDS broadcast
        if (t == 0) {
            int r = kpbase + k;
            g_kp[r*3+0] = w.x; g_kp[r*3+1] = w.y; g_kp[r*3+2] = w.z;
            coords_out[r*4+0] = (float)b;
            coords_out[r*4+1] = w.x; coords_out[r*4+2] = w.y; coords_out[r*4+3] = w.z;
        }
        if (k == K-1) break;

        unsigned long long wx = pk2(w.x, w.x);
        unsigned long long wy = pk2(w.y, w.y);
        unsigned long long wz = pk2(w.z, w.z);
        float best = -1.0f; int bi = 0x7fffffff;
        #pragma unroll
        for (int p = 0; p < P; p++) {
            unsigned long long dx = addx2(Xn[p], wx);   // (w-x): square == (x-w)^2 exactly
            unsigned long long dy = addx2(Yn[p], wy);
            unsigned long long dz = addx2(Zn[p], wz);
            unsigned long long d2 = addx2(addx2(mulx2(dx,dx), mulx2(dy,dy)), mulx2(dz,dz));
            float dl, dh; upk2(d2, dl, dh);
            float n0 = fminf(D[2*p],   dl); D[2*p]   = n0;
            float n1 = fminf(D[2*p+1], dh); D[2*p+1] = n1;
            // ascending slot order + strict '>' keeps smallest index on ties
            if (n0 > best) { best = n0; bi = (2*p)*256 + t; }
            if (n1 > best) { best = n1; bi = (2*p+1)*256 + t; }
        }
        best = fmaxf(best, 0.0f);            // all-invalid thread: bi stays huge
        unsigned u  = __float_as_uint(best); // d>=0 => bits order-isomorphic
        unsigned vm = redux_maxu(u);
        unsigned cand = (u == vm) ? (unsigned)bi : 0x7fffffffu;
        unsigned im = redux_minu(cand);
        int par = k & 1;
        if (lane == 0) { sv[par][warp] = vm; si[par][warp] = im; }
        __syncthreads();
        unsigned v2 = sv[par][lane & 7];
        unsigned i2 = si[par][lane & 7];
        unsigned g  = redux_maxu(v2);
        unsigned c2 = (v2 == g) ? i2 : 0x7fffffffu;
        sel = (int)redux_minu(c2);
    }
}

__global__ void __launch_bounds__(256,1) fps_kernel(const float* __restrict__ pts,
                                                    const float* __restrict__ rng,
                                                    float* __restrict__ coords_out) {
    extern __shared__ float4 scmp[];
    __shared__ unsigned sv[2][8];
    __shared__ unsigned si[2][8];
    __shared__ int wsum[8];
    __shared__ int s_tot;

    int run = blockIdx.x, b = run/3, band = run - b*3;
    int t = threadIdx.x;
    int lane = t & 31, warp = t >> 5;

    // ---- stable band compaction: 64 points per thread (contiguous) ----
    const float4* R4 = (const float4*)(rng + (size_t)b*NPTS) + t*16;
    unsigned long long bits = 0; int cnt = 0;
    #pragma unroll
    for (int q = 0; q < 16; q++) {
        float4 r4 = R4[q];
        float rr[4] = {r4.x, r4.y, r4.z, r4.w};
        #pragma unroll
        for (int u = 0; u < 4; u++) {
            float r = rr[u];
            bool sh = (r > 0.0f) && (r < 25.0f);
            bool lg = (r > 45.0f);
            bool v = (band == 0) ? sh : ((band == 2) ? lg : (!lg && !sh));
            if (v) { bits |= (1ull << (q*4+u)); cnt++; }
        }
    }
    int inc = cnt;
    #pragma unroll
    for (int off = 1; off < 32; off <<= 1) {
        int o = __shfl_up_sync(FULLM, inc, off);
        if (lane >= off) inc += o;
    }
    if (lane == 31) wsum[warp] = inc;
    __syncthreads();
    if (warp == 0 && lane < 8) {
        int v = wsum[lane];
        #pragma unroll
        for (int off = 1; off < 8; off <<= 1) {
            int o = __shfl_up_sync(0xffu, v, off);
            if (lane >= off) v += o;
        }
        wsum[lane] = v;
        if (lane == 7) s_tot = v;
    }
    __syncthreads();
    int off0 = inc - cnt + (warp ? wsum[warp-1] : 0);
    const float* PP = pts + (size_t)b*NPTS*5;
    for (int u = 0; u < 64; u++) {
        if ((bits >> u) & 1ull) {
            if (off0 < CMPN) {
                const float* p = PP + (size_t)(t*64 + u)*5;
                scmp[off0] = make_float4(p[1], p[2], p[3], p[4]);
            }
            off0++;
        }
    }
    int M = min(s_tot, CMPN);
    for (int i = M + t; i < CMPN; i += 256)
        scmp[i] = make_float4(1e15f, 1e15f, 1e15f, 0.f);
    // SoA points for downstream kernels (spread across the 6 blocks)
    for (int i = run*256 + t; i < BATCH*NPTS; i += 6*256) {
        const float* p = pts + (size_t)i*5;
        g_pts[i] = make_float4(p[1], p[2], p[3], p[4]);
    }
    __syncthreads();

    // ---- FPS dispatch sized to the band population ----
    int K = (band == 0) ? 1024 : 512;
    int kpbase = b*KTOT + (band==0 ? 0 : (band==1 ? 1024 : 1536));
    int P = min(16, ((M + 1023) >> 10) * 2);   // even, 512*P >= M
    switch (P) {
        case 2:  fps_body<2>(b, K, kpbase, M, coords_out, sv, si); break;
        case 4:  fps_body<4>(b, K, kpbase, M, coords_out, sv, si); break;
        case 6:  fps_body<6>(b, K, kpbase, M, coords_out, sv, si); break;
        case 8:  fps_body<8>(b, K, kpbase, M, coords_out, sv, si); break;
        case 10: fps_body<10>(b, K, kpbase, M, coords_out, sv, si); break;
        case 12: fps_body<12>(b, K, kpbase, M, coords_out, sv, si); break;
        case 14: fps_body<14>(b, K, kpbase, M, coords_out, sv, si); break;
        default: fps_body<16>(b, K, kpbase, M, coords_out, sv, si); break;
    }
}

// ==================================================================
// fused: ball-query scan (blocks 0..255) + BEV bilinear (blocks 256..)
// ==================================================================
__global__ void __launch_bounds__(512) bevscan_kernel(const float* __restrict__ sf,
                                                      float* __restrict__ outFeats) {
    __shared__ float4 spts[2048];
    __shared__ int   sidx[16][2][16];
    int tid = threadIdx.x;

    if (blockIdx.x >= SCANB) {
        // ---- BEV bilinear: 2 rows per block, direct CHW gather ----
        int row = ((int)blockIdx.x - SCANB)*2 + (tid >> 8);
        int c = tid & 255;
        int b = row >> 11;
        float kx = g_kp[row*3+0], ky = g_kp[row*3+1];
        float xi = ((kx - 0.0f)     / 0.05f) / 8.0f;
        float yi = ((ky - (-40.0f)) / 0.05f) / 8.0f;
        int x0 = (int)floorf(xi); int x1 = x0 + 1;
        int y0 = (int)floorf(yi); int y1 = y0 + 1;
        x0 = min(max(x0, 0), WBEV-1); x1 = min(max(x1, 0), WBEV-1);
        y0 = min(max(y0, 0), HBEV-1); y1 = min(max(y1, 0), HBEV-1);
        float x0f = (float)x0, x1f = (float)x1, y0f = (float)y0, y1f = (float)y1;
        float wa = (x1f - xi)*(y1f - yi);
        float wb = (x1f - xi)*(yi - y0f);
        float wc = (xi - x0f)*(y1f - yi);
        float wd = (xi - x0f)*(yi - y0f);
        const float* ch = sf + ((size_t)b*CBEV + c)*HW;
        float Ia = __ldg(ch + y0*WBEV + x0);
        float Ib = __ldg(ch + y1*WBEV + x0);
        float Ic = __ldg(ch + y0*WBEV + x1);
        float Id = __ldg(ch + y1*WBEV + x1);
        outFeats[(size_t)row*288 + c] = Ia*wa + Ib*wb + Ic*wc + Id*wd;
        return;
    }

    // ---- ball-query scan: gated bookkeeping, 2 pts/lane ----
    int w = tid >> 5, lane = tid & 31;
    int row = blockIdx.x*16 + w;
    int b = row >> 11;
    float kx = g_kp[row*3], ky = g_kp[row*3+1], kz = g_kp[row*3+2];
    unsigned long long nkx = pk2(-kx, -kx), nky = pk2(-ky, -ky), nkz = pk2(-kz, -kz);
    const float4* P = g_pts + (size_t)b*NPTS;
    unsigned lt  = (1u << lane) - 1u;
    unsigned lte = lt | (1u << lane);

    int c1 = 0, c2 = 0;
    for (int base0 = 0; base0 < NPTS; base0 += 2048) {
        __syncthreads();
        #pragma unroll
        for (int i = 0; i < 4; i++) spts[tid + i*512] = P[base0 + tid + i*512];
        __syncthreads();
        if (c1 >= 16 && c2 >= 16) continue;
        for (int off = 0; off < 2048; off += 64) {
            float4 p0 = spts[off + 2*lane];
            float4 p1 = spts[off + 2*lane + 1];
            unsigned long long dx = addx2(pk2(p0.x, p1.x), nkx);
            unsigned long long dy = addx2(pk2(p0.y, p1.y), nky);
            unsigned long long dz = addx2(pk2(p0.z, p1.z), nkz);
            unsigned long long d2 = addx2(addx2(mulx2(dx,dx), mulx2(dy,dy)), mulx2(dz,dz));
            float da, db; upk2(d2, da, db);
            bool v2a = da < 4.0f, v2b = db < 4.0f;
            if (__ballot_sync(FULLM, v2a || v2b)) {
                bool v1a = da < 1.0f, v1b = db < 1.0f;
                unsigned m1e = __ballot_sync(FULLM, v1a);
                unsigned m1o = __ballot_sync(FULLM, v1b);
                unsigned m2e = __ballot_sync(FULLM, v2a);
                unsigned m2o = __ballot_sync(FULLM, v2b);
                int gi = base0 + off + 2*lane;
                if (c1 < 16 && (m1e | m1o)) {
                    int re = __popc(m1e & lt)  + __popc(m1o & lt);
                    int ro = __popc(m1e & lte) + __popc(m1o & lt);
                    if (v1a && c1 + re < 16) sidx[w][0][c1+re] = gi;
                    if (v1b && c1 + ro < 16) sidx[w][0][c1+ro] = gi + 1;
                    c1 = min(c1 + __popc(m1e) + __popc(m1o), 16);
                }
                if (c2 < 16) {
                    int re = __popc(m2e & lt)  + __popc(m2o & lt);
                    int ro = __popc(m2e & lte) + __popc(m2o & lt);
                    if (v2a && c2 + re < 16) sidx[w][1][c2+re] = gi;
                    if (v2b && c2 + ro < 16) sidx[w][1][c2+ro] = gi + 1;
                    c2 = min(c2 + __popc(m2e) + __popc(m2o), 16);
                }
                if (c1 >= 16 && c2 >= 16) break;
            }
        }
    }
    __syncwarp();
    if (lane < 2) g_ballcnt[row*2 + lane] = lane ? c2 : c1;
    int rI = lane >> 4, s = lane & 15;
    int cnt = rI ? c2 : c1;
    g_ballidx[row*32 + lane] = (s < cnt) ? sidx[w][rI][s] : (cnt > 0 ? sidx[w][rI][0] : 0);
}

// ---------------- MLP + maxpool over gathered neighbors ----------------
__global__ void __launch_bounds__(256) sa_mlp_kernel(
        const float* __restrict__ w0, const float* __restrict__ bn0,
        const float* __restrict__ w1, const float* __restrict__ bn1,
        float* __restrict__ outFeats) {
    __shared__ float sw0[128];
    __shared__ float sw1[512];
    __shared__ float sb0s[32], sb0m[32], sb0b[32];
    __shared__ float sb1s[32], sb1m[32], sb1b[32];
    int tid = threadIdx.x;
    if (tid < 128) sw0[tid] = w0[tid];
    for (int i = tid; i < 512; i += 256) sw1[i] = w1[i];
    if (tid < 32) {
        int br = tid >> 4, c = tid & 15;
        float g = bn0[br*64 + c], be = bn0[br*64+16+c], m = bn0[br*64+32+c], v = bn0[br*64+48+c];
        sb0s[tid] = g * (1.0f/sqrtf(v + 1e-5f)); sb0m[tid] = m; sb0b[tid] = be;
        g = bn1[br*64 + c]; be = bn1[br*64+16+c]; m = bn1[br*64+32+c]; v = bn1[br*64+48+c];
        sb1s[tid] = g * (1.0f/sqrtf(v + 1e-5f)); sb1m[tid] = m; sb1b[tid] = be;
    }
    __syncthreads();

    int w = tid >> 5, lane = tid & 31;
    int row = blockIdx.x*8 + w;
    int b = row >> 11;
    float kx = g_kp[row*3], ky = g_kp[row*3+1], kz = g_kp[row*3+2];
    const float4* P = g_pts + (size_t)b*NPTS;

    int rI = lane >> 4, s = lane & 15;
    int cnt = g_ballcnt[row*2 + rI];
    float gx = 0.f, gy = 0.f, gz = 0.f, gi = 0.f;
    if (cnt > 0) {
        int id = g_ballidx[row*32 + rI*16 + ((s < cnt) ? s : 0)];
        float4 p = P[id];
        gx = p.x - kx; gy = p.y - ky; gz = p.z - kz; gi = p.w;
    }
    const float* W0  = sw0  + rI*64;
    const float* W1  = sw1  + rI*256;
    const float* B0s = sb0s + rI*16; const float* B0m = sb0m + rI*16; const float* B0b = sb0b + rI*16;
    const float* B1s = sb1s + rI*16; const float* B1m = sb1m + rI*16; const float* B1b = sb1b + rI*16;

    float h1[16];
    #pragma unroll
    for (int c = 0; c < 16; c++) {
        float a = gx*W0[c] + gy*W0[16+c] + gz*W0[32+c] + gi*W0[48+c];
        h1[c] = fmaxf((a - B0m[c])*B0s[c] + B0b[c], 0.0f);
    }
    float h2[16];
    #pragma unroll
    for (int c = 0; c < 16; c++) {
        float a = 0.f;
        #pragma unroll
        for (int k = 0; k < 16; k++) a += h1[k]*W1[k*16 + c];
        h2[c] = fmaxf((a - B1m[c])*B1s[c] + B1b[c], 0.0f);
    }
    #pragma unroll
    for (int off = 8; off; off >>= 1) {
        #pragma unroll
        for (int c = 0; c < 16; c++)
            h2[c] = fmaxf(h2[c], __shfl_xor_sync(FULLM, h2[c], off));
    }
    if (s == 0) {
        float* o = outFeats + (size_t)row*288 + 256 + rI*16;
        #pragma unroll
        for (int c = 0; c < 16; c++) o[c] = h2[c];
    }
}

// ---------------- fusion: [4096,288] @ [288,128] + BN + ReLU ----------------
__global__ void __launch_bounds__(128) fusion_kernel(
        const float* __restrict__ feats, const float* __restrict__ fw,
        const float* __restrict__ fbn, float* __restrict__ out) {
    __shared__ float sr[16*288];
    int tid = threadIdx.x;
    size_t row0 = (size_t)blockIdx.x * 16;
    for (int i = tid; i < 16*288; i += 128) sr[i] = feats[row0*288 + i];
    __syncthreads();
    float acc[16];
    #pragma unroll
    for (int r = 0; r < 16; r++) acc[r] = 0.f;
    for (int k = 0; k < 288; k++) {
        float wv = __ldg(fw + (size_t)k*128 + tid);
        #pragma unroll
        for (int r = 0; r < 16; r++) acc[r] += sr[r*288 + k] * wv;
    }
    float g = fbn[tid], be = fbn[128+tid], m = fbn[256+tid], v = fbn[384+tid];
    float sc = g * (1.0f/sqrtf(v + 1e-5f));
    #pragma unroll
    for (int r = 0; r < 16; r++)
        out[(row0 + r)*128 + tid] = fmaxf((acc[r] - m)*sc + be, 0.f);
}

// ---------------- launch ----------------
extern "C" void kernel_launch(void* const* d_in, const int* in_sizes, int n_in,
                              void* d_out, int out_size) {
    const float* points = (const float*)d_in[0];
    const float* rng    = (const float*)d_in[1];
    const float* sf     = (const float*)d_in[2];
    const float* sa_w0  = (const float*)d_in[3];
    const float* sa_bn0 = (const float*)d_in[4];
    const float* sa_w1  = (const float*)d_in[5];
    const float* sa_bn1 = (const float*)d_in[6];
    const float* fw     = (const float*)d_in[7];
    const float* fbn    = (const float*)d_in[8];
    float* out = (float*)d_out;

    float* fused  = out;                                          // [4096,128]
    float* feats  = out + (size_t)NROWS*128;                      // [4096,288]
    float* coords = out + (size_t)NROWS*128 + (size_t)NROWS*288;  // [4096,4]

    const int FPS_SMEM = CMPN * sizeof(float4);   // 128 KB
    static int smem_set = 0;
    if (!smem_set) {
        cudaFuncSetAttribute(fps_kernel, cudaFuncAttributeMaxDynamicSharedMemorySize, FPS_SMEM);
        smem_set = 1;
    }

    fps_kernel<<<6, 256, FPS_SMEM>>>(points, rng, coords);
    bevscan_kernel<<<SCANB + NROWS/2, 512>>>(sf, feats);
    sa_mlp_kernel<<<NROWS/8, 256>>>(sa_w0, sa_bn0, sa_w1, sa_bn1, feats);
    fusion_kernel<<<NROWS/16, 128>>>(feats, fw, fbn, fused);
}

// round 5
// speedup vs baseline: 3.8887x; 1.2377x over previous
#include <cuda_runtime.h>
#include <math.h>

#define NPTS   16384
#define BATCH  2
#define HBEV   200
#define WBEV   176
#define CBEV   256
#define HW     (HBEV*WBEV)
#define KTOT   2048
#define NROWS  (BATCH*KTOT)
#define CMPN   8192
#define FULLM  0xffffffffu

// ---------------- static device scratch ----------------
__device__ float4 g_pts[BATCH*NPTS];       // SoA points: x,y,z,intensity
__device__ float  g_kp[NROWS*3];           // keypoint coords
__device__ int    g_ballidx[NROWS*32];     // [row][2][16] neighbor indices
__device__ int    g_ballcnt[NROWS*2];      // [row][2] capped counts

// ---------------- packed f32x2 + redux helpers ----------------
__device__ __forceinline__ unsigned long long pk2(float lo, float hi) {
    unsigned long long r; asm("mov.b64 %0, {%1, %2};" : "=l"(r) : "f"(lo), "f"(hi)); return r;
}
__device__ __forceinline__ void upk2(unsigned long long v, float& lo, float& hi) {
    asm("mov.b64 {%0, %1}, %2;" : "=f"(lo), "=f"(hi) : "l"(v));
}
__device__ __forceinline__ unsigned long long addx2(unsigned long long a, unsigned long long b) {
    unsigned long long r; asm("add.rn.f32x2 %0, %1, %2;" : "=l"(r) : "l"(a), "l"(b)); return r;
}
__device__ __forceinline__ unsigned long long mulx2(unsigned long long a, unsigned long long b) {
    unsigned long long r; asm("mul.rn.f32x2 %0, %1, %2;" : "=l"(r) : "l"(a), "l"(b)); return r;
}
__device__ __forceinline__ unsigned redux_maxu(unsigned v) {
    unsigned r; asm("redux.sync.max.u32 %0, %1, 0xffffffff;" : "=r"(r) : "r"(v)); return r;
}
__device__ __forceinline__ unsigned redux_minu(unsigned v) {
    unsigned r; asm("redux.sync.min.u32 %0, %1, 0xffffffff;" : "=r"(r) : "r"(v)); return r;
}

// ---------------- prep: AoS points -> float4 SoA (many blocks, fast) ----------------
__global__ void __launch_bounds__(512) prep_pts_kernel(const float* __restrict__ pts) {
    int i = blockIdx.x*512 + threadIdx.x;
    const float* p = pts + (size_t)i*5;
    g_pts[i] = make_float4(p[1], p[2], p[3], p[4]);
}

// ==================================================================
// FPS: compaction + furthest-point sampling, one block per band.
// ==================================================================
template<int P>
__device__ __forceinline__ void fps_body(int b, int K, int kpbase, int M,
                                         float* __restrict__ coords_out,
                                         unsigned (*sv)[8], unsigned (*si)[8]) {
    extern __shared__ float4 scmp[];
    int t = threadIdx.x;
    int lane = t & 31, warp = t >> 5;

    unsigned long long Xn[P], Yn[P], Zn[P];   // negated coords
    float D[2*P];
    #pragma unroll
    for (int p = 0; p < P; p++) {
        float4 a = scmp[(2*p)*256 + t];
        float4 c = scmp[(2*p+1)*256 + t];
        Xn[p] = pk2(-a.x, -c.x); Yn[p] = pk2(-a.y, -c.y); Zn[p] = pk2(-a.z, -c.z);
        D[2*p]   = ((2*p)*256 + t   < M) ? 1e10f : -1.0f;
        D[2*p+1] = ((2*p+1)*256 + t < M) ? 1e10f : -1.0f;
    }

    int sel = 0;   // first valid point = compacted index 0
    for (int k = 0; ; k++) {
        float4 w = scmp[sel];                // LDS broadcast
        if (t == 0) {
            int r = kpbase + k;
            g_kp[r*3+0] = w.x; g_kp[r*3+1] = w.y; g_kp[r*3+2] = w.z;
            coords_out[r*4+0] = (float)b;
            coords_out[r*4+1] = w.x; coords_out[r*4+2] = w.y; coords_out[r*4+3] = w.z;
        }
        if (k == K-1) break;

        unsigned long long wx = pk2(w.x, w.x);
        unsigned long long wy = pk2(w.y, w.y);
        unsigned long long wz = pk2(w.z, w.z);
        float bm[4] = {-1.f, -1.f, -1.f, -1.f};
        #pragma unroll
        for (int p = 0; p < P; p++) {
            unsigned long long dx = addx2(Xn[p], wx);   // (w-x): square == (x-w)^2 exactly
            unsigned long long dy = addx2(Yn[p], wy);
            unsigned long long dz = addx2(Zn[p], wz);
            unsigned long long d2 = addx2(addx2(mulx2(dx,dx), mulx2(dy,dy)), mulx2(dz,dz));
            float dl, dh; upk2(d2, dl, dh);
            float n0 = fminf(D[2*p],   dl); D[2*p]   = n0;
            float n1 = fminf(D[2*p+1], dh); D[2*p+1] = n1;
            bm[p & 3] = fmaxf(bm[p & 3], fmaxf(n0, n1));
        }
        float best = fmaxf(fmaxf(bm[0], bm[1]), fmaxf(bm[2], bm[3]));
        best = fmaxf(best, 0.0f);            // all-invalid thread: stays non-winner
        unsigned myidx = 0x7fffffffu;
        #pragma unroll
        for (int j = 2*P-1; j >= 0; j--)
            if (D[j] == best) myidx = (unsigned)(j*256 + t);   // smallest j wins

        unsigned u  = __float_as_uint(best); // d>=0 => bits order-isomorphic
        unsigned vm = redux_maxu(u);
        unsigned cand = (u == vm) ? myidx : 0x7fffffffu;
        unsigned im = redux_minu(cand);
        int par = k & 1;
        if (lane == 0) { sv[par][warp] = vm; si[par][warp] = im; }
        __syncthreads();
        unsigned v2 = sv[par][lane & 7];
        unsigned i2 = si[par][lane & 7];
        unsigned g  = redux_maxu(v2);
        unsigned c2 = (v2 == g) ? i2 : 0x7fffffffu;
        sel = (int)redux_minu(c2);
    }
}

__global__ void __launch_bounds__(256,1) fps_kernel(const float* __restrict__ pts,
                                                    const float* __restrict__ rng,
                                                    float* __restrict__ coords_out) {
    extern __shared__ float4 scmp[];
    __shared__ unsigned sv[2][8];
    __shared__ unsigned si[2][8];
    __shared__ int wsum[8];
    __shared__ int s_tot;

    int run = blockIdx.x, b = run/3, band = run - b*3;
    int t = threadIdx.x;
    int lane = t & 31, warp = t >> 5;

    // ---- stable band compaction: 64 points per thread (contiguous) ----
    const float4* R4 = (const float4*)(rng + (size_t)b*NPTS) + t*16;
    unsigned long long bits = 0; int cnt = 0;
    #pragma unroll
    for (int q = 0; q < 16; q++) {
        float4 r4 = R4[q];
        float rr[4] = {r4.x, r4.y, r4.z, r4.w};
        #pragma unroll
        for (int u = 0; u < 4; u++) {
            float r = rr[u];
            bool sh = (r > 0.0f) && (r < 25.0f);
            bool lg = (r > 45.0f);
            bool v = (band == 0) ? sh : ((band == 2) ? lg : (!lg && !sh));
            if (v) { bits |= (1ull << (q*4+u)); cnt++; }
        }
    }
    int inc = cnt;
    #pragma unroll
    for (int off = 1; off < 32; off <<= 1) {
        int o = __shfl_up_sync(FULLM, inc, off);
        if (lane >= off) inc += o;
    }
    if (lane == 31) wsum[warp] = inc;
    __syncthreads();
    if (warp == 0 && lane < 8) {
        int v = wsum[lane];
        #pragma unroll
        for (int off = 1; off < 8; off <<= 1) {
            int o = __shfl_up_sync(0xffu, v, off);
            if (lane >= off) v += o;
        }
        wsum[lane] = v;
        if (lane == 7) s_tot = v;
    }
    __syncthreads();
    int off0 = inc - cnt + (warp ? wsum[warp-1] : 0);
    const float* PP = pts + (size_t)b*NPTS*5;
    for (int u = 0; u < 64; u++) {
        if ((bits >> u) & 1ull) {
            if (off0 < CMPN) {
                const float* p = PP + (size_t)(t*64 + u)*5;
                scmp[off0] = make_float4(p[1], p[2], p[3], p[4]);
            }
            off0++;
        }
    }
    int M = min(s_tot, CMPN);
    for (int i = M + t; i < CMPN; i += 256)
        scmp[i] = make_float4(1e15f, 1e15f, 1e15f, 0.f);
    __syncthreads();

    // ---- FPS dispatch sized to the band population ----
    int K = (band == 0) ? 1024 : 512;
    int kpbase = b*KTOT + (band==0 ? 0 : (band==1 ? 1024 : 1536));
    int P = min(16, ((M + 1023) >> 10) * 2);   // even, 512*P >= M
    switch (P) {
        case 2:  fps_body<2>(b, K, kpbase, M, coords_out, sv, si); break;
        case 4:  fps_body<4>(b, K, kpbase, M, coords_out, sv, si); break;
        case 6:  fps_body<6>(b, K, kpbase, M, coords_out, sv, si); break;
        case 8:  fps_body<8>(b, K, kpbase, M, coords_out, sv, si); break;
        case 10: fps_body<10>(b, K, kpbase, M, coords_out, sv, si); break;
        case 12: fps_body<12>(b, K, kpbase, M, coords_out, sv, si); break;
        case 14: fps_body<14>(b, K, kpbase, M, coords_out, sv, si); break;
        default: fps_body<16>(b, K, kpbase, M, coords_out, sv, si); break;
    }
}

// ==================================================================
// scan: ball-query, 2 keypoints per warp, SoA xyz float2 tiles
// ==================================================================
__global__ void __launch_bounds__(512) scan_kernel() {
    __shared__ float2 sx[1024], sy[1024], sz[1024];
    __shared__ int sidx[16][2][2][16];     // [warp][kp][radius][slot]
    int tid = threadIdx.x;
    int w = tid >> 5, lane = tid & 31;
    int row0 = blockIdx.x*32 + w*2;
    int b = row0 >> 11;
    const float4* P = g_pts + (size_t)b*NPTS;

    unsigned long long nkx[2], nky[2], nkz[2];
    #pragma unroll
    for (int kp = 0; kp < 2; kp++) {
        float kx = g_kp[(row0+kp)*3], ky = g_kp[(row0+kp)*3+1], kz = g_kp[(row0+kp)*3+2];
        nkx[kp] = pk2(-kx, -kx); nky[kp] = pk2(-ky, -ky); nkz[kp] = pk2(-kz, -kz);
    }
    unsigned lt  = (1u << lane) - 1u;
    unsigned lte = lt | (1u << lane);

    int c1[2] = {0,0}, c2[2] = {0,0};
    for (int base0 = 0; base0 < NPTS; base0 += 2048) {
        __syncthreads();
        #pragma unroll
        for (int i = 0; i < 2; i++) {
            int j = tid + i*512;            // float2 slot
            float4 p0 = P[base0 + 2*j];
            float4 p1 = P[base0 + 2*j + 1];
            sx[j] = make_float2(p0.x, p1.x);
            sy[j] = make_float2(p0.y, p1.y);
            sz[j] = make_float2(p0.z, p1.z);
        }
        __syncthreads();
        if (c1[0] >= 16 && c2[0] >= 16 && c1[1] >= 16 && c2[1] >= 16) continue;
        for (int o32 = 0; o32 < 1024; o32 += 32) {
            float2 vx = sx[o32 + lane], vy = sy[o32 + lane], vz = sz[o32 + lane];
            unsigned long long px = pk2(vx.x, vx.y);
            unsigned long long py = pk2(vy.x, vy.y);
            unsigned long long pz = pk2(vz.x, vz.y);
            float da[2], db[2];
            #pragma unroll
            for (int kp = 0; kp < 2; kp++) {
                unsigned long long dx = addx2(px, nkx[kp]);
                unsigned long long dy = addx2(py, nky[kp]);
                unsigned long long dz = addx2(pz, nkz[kp]);
                unsigned long long d2 = addx2(addx2(mulx2(dx,dx), mulx2(dy,dy)), mulx2(dz,dz));
                upk2(d2, da[kp], db[kp]);
            }
            bool any = (da[0] < 4.0f) || (db[0] < 4.0f) || (da[1] < 4.0f) || (db[1] < 4.0f);
            if (__ballot_sync(FULLM, any)) {
                int gi = base0 + 2*(o32 + lane);
                #pragma unroll
                for (int kp = 0; kp < 2; kp++) {
                    bool v2a = da[kp] < 4.0f, v2b = db[kp] < 4.0f;
                    bool v1a = da[kp] < 1.0f, v1b = db[kp] < 1.0f;
                    unsigned m1e = __ballot_sync(FULLM, v1a);
                    unsigned m1o = __ballot_sync(FULLM, v1b);
                    unsigned m2e = __ballot_sync(FULLM, v2a);
                    unsigned m2o = __ballot_sync(FULLM, v2b);
                    if (c1[kp] < 16 && (m1e | m1o)) {
                        int re = __popc(m1e & lt)  + __popc(m1o & lt);
                        int ro = __popc(m1e & lte) + __popc(m1o & lt);
                        if (v1a && c1[kp] + re < 16) sidx[w][kp][0][c1[kp]+re] = gi;
                        if (v1b && c1[kp] + ro < 16) sidx[w][kp][0][c1[kp]+ro] = gi + 1;
                        c1[kp] = min(c1[kp] + __popc(m1e) + __popc(m1o), 16);
                    }
                    if (c2[kp] < 16 && (m2e | m2o)) {
                        int re = __popc(m2e & lt)  + __popc(m2o & lt);
                        int ro = __popc(m2e & lte) + __popc(m2o & lt);
                        if (v2a && c2[kp] + re < 16) sidx[w][kp][1][c2[kp]+re] = gi;
                        if (v2b && c2[kp] + ro < 16) sidx[w][kp][1][c2[kp]+ro] = gi + 1;
                        c2[kp] = min(c2[kp] + __popc(m2e) + __popc(m2o), 16);
                    }
                }
                if (c1[0] >= 16 && c2[0] >= 16 && c1[1] >= 16 && c2[1] >= 16) break;
            }
        }
    }
    __syncwarp();
    int rI = lane >> 4, s = lane & 15;
    #pragma unroll
    for (int kp = 0; kp < 2; kp++) {
        int row = row0 + kp;
        if (lane < 2) g_ballcnt[row*2 + lane] = lane ? c2[kp] : c1[kp];
        int cnt = rI ? c2[kp] : c1[kp];
        g_ballidx[row*32 + lane] = (s < cnt) ? sidx[w][kp][rI][s]
                                             : (cnt > 0 ? sidx[w][kp][rI][0] : 0);
    }
}

// ==================================================================
// fusion v2: BEV bilinear + SA MLP + GEMM + BN + ReLU, 4 rows/block
// ==================================================================
__global__ void __launch_bounds__(128) fusion_kernel(
        const float* __restrict__ sf,
        const float* __restrict__ w0, const float* __restrict__ bn0,
        const float* __restrict__ w1, const float* __restrict__ bn1,
        const float* __restrict__ fw, const float* __restrict__ fbn,
        float* __restrict__ feats, float* __restrict__ out) {
    __shared__ float sr[4*288];
    __shared__ float sw0[128];
    __shared__ float sw1[512];
    __shared__ float sb0s[32], sb0m[32], sb0b[32];
    __shared__ float sb1s[32], sb1m[32], sb1b[32];
    int tid = threadIdx.x;
    int row0 = blockIdx.x*4;
    int b = row0 >> 11;

    sw0[tid] = w0[tid];
    #pragma unroll
    for (int i = 0; i < 4; i++) sw1[tid + i*128] = w1[tid + i*128];
    if (tid < 32) {
        int br = tid >> 4, c = tid & 15;
        float g = bn0[br*64 + c], be = bn0[br*64+16+c], m = bn0[br*64+32+c], v = bn0[br*64+48+c];
        sb0s[tid] = g * (1.0f/sqrtf(v + 1e-5f)); sb0m[tid] = m; sb0b[tid] = be;
        g = bn1[br*64 + c]; be = bn1[br*64+16+c]; m = bn1[br*64+32+c]; v = bn1[br*64+48+c];
        sb1s[tid] = g * (1.0f/sqrtf(v + 1e-5f)); sb1m[tid] = m; sb1b[tid] = be;
    }

    // ---- phase A: BEV bilinear, direct CHW gather ----
    #pragma unroll
    for (int r = 0; r < 4; r++) {
        int row = row0 + r;
        float kx = g_kp[row*3+0], ky = g_kp[row*3+1];
        float xi = ((kx - 0.0f)     / 0.05f) / 8.0f;
        float yi = ((ky - (-40.0f)) / 0.05f) / 8.0f;
        int x0 = (int)floorf(xi); int x1 = x0 + 1;
        int y0 = (int)floorf(yi); int y1 = y0 + 1;
        x0 = min(max(x0, 0), WBEV-1); x1 = min(max(x1, 0), WBEV-1);
        y0 = min(max(y0, 0), HBEV-1); y1 = min(max(y1, 0), HBEV-1);
        float x0f = (float)x0, x1f = (float)x1, y0f = (float)y0, y1f = (float)y1;
        float wa = (x1f - xi)*(y1f - yi);
        float wb = (x1f - xi)*(yi - y0f);
        float wc = (xi - x0f)*(y1f - yi);
        float wd = (xi - x0f)*(yi - y0f);
        #pragma unroll
        for (int h = 0; h < 2; h++) {
            int c = tid + h*128;
            const float* ch = sf + ((size_t)b*CBEV + c)*HW;
            float Ia = __ldg(ch + y0*WBEV + x0);
            float Ib = __ldg(ch + y1*WBEV + x0);
            float Ic = __ldg(ch + y0*WBEV + x1);
            float Id = __ldg(ch + y1*WBEV + x1);
            float val = Ia*wa + Ib*wb + Ic*wc + Id*wd;
            sr[r*288 + c] = val;
            feats[(size_t)row*288 + c] = val;
        }
    }
    __syncthreads();

    // ---- phase B: SA MLP + maxpool (8 groups of 16 threads) ----
    {
        int g = tid >> 4;            // 0..7 = (row 0..3) x (radius 0..1)
        int r = g >> 1, rI = g & 1, s = tid & 15;
        int row = row0 + r;
        float kx = g_kp[row*3], ky = g_kp[row*3+1], kz = g_kp[row*3+2];
        const float4* P = g_pts + (size_t)b*NPTS;
        int cnt = g_ballcnt[row*2 + rI];
        float gx = 0.f, gy = 0.f, gz = 0.f, gi = 0.f;
        if (cnt > 0) {
            int id = g_ballidx[row*32 + rI*16 + ((s < cnt) ? s : 0)];
            float4 p = P[id];
            gx = p.x - kx; gy = p.y - ky; gz = p.z - kz; gi = p.w;
        }
        const float* W0  = sw0  + rI*64;
        const float* W1  = sw1  + rI*256;
        const float* B0s = sb0s + rI*16; const float* B0m = sb0m + rI*16; const float* B0b = sb0b + rI*16;
        const float* B1s = sb1s + rI*16; const float* B1m = sb1m + rI*16; const float* B1b = sb1b + rI*16;

        float h1[16];
        #pragma unroll
        for (int c = 0; c < 16; c++) {
            float a = gx*W0[c] + gy*W0[16+c] + gz*W0[32+c] + gi*W0[48+c];
            h1[c] = fmaxf((a - B0m[c])*B0s[c] + B0b[c], 0.0f);
        }
        float h2[16];
        #pragma unroll
        for (int c = 0; c < 16; c++) {
            float a = 0.f;
            #pragma unroll
            for (int k = 0; k < 16; k++) a += h1[k]*W1[k*16 + c];
            h2[c] = fmaxf((a - B1m[c])*B1s[c] + B1b[c], 0.0f);
        }
        #pragma unroll
        for (int off = 8; off; off >>= 1) {   // maxpool within 16-lane group
            #pragma unroll
            for (int c = 0; c < 16; c++)
                h2[c] = fmaxf(h2[c], __shfl_xor_sync(FULLM, h2[c], off));
        }
        if (s == 0) {
            #pragma unroll
            for (int c = 0; c < 16; c++) {
                sr[r*288 + 256 + rI*16 + c] = h2[c];
                feats[(size_t)row*288 + 256 + rI*16 + c] = h2[c];
            }
        }
    }
    __syncthreads();

    // ---- phase C: GEMM [4,288]@[288,128] + BN + ReLU ----
    float acc[4] = {0.f, 0.f, 0.f, 0.f};
    for (int k = 0; k < 288; k++) {
        float wv = __ldg(fw + (size_t)k*128 + tid);
        #pragma unroll
        for (int r = 0; r < 4; r++) acc[r] += sr[r*288 + k] * wv;
    }
    float g = fbn[tid], be = fbn[128+tid], m = fbn[256+tid], v = fbn[384+tid];
    float sc = g * (1.0f/sqrtf(v + 1e-5f));
    #pragma unroll
    for (int r = 0; r < 4; r++)
        out[(size_t)(row0 + r)*128 + tid] = fmaxf((acc[r] - m)*sc + be, 0.f);
}

// ---------------- launch ----------------
extern "C" void kernel_launch(void* const* d_in, const int* in_sizes, int n_in,
                              void* d_out, int out_size) {
    const float* points = (const float*)d_in[0];
    const float* rng    = (const float*)d_in[1];
    const float* sf     = (const float*)d_in[2];
    const float* sa_w0  = (const float*)d_in[3];
    const float* sa_bn0 = (const float*)d_in[4];
    const float* sa_w1  = (const float*)d_in[5];
    const float* sa_bn1 = (const float*)d_in[6];
    const float* fw     = (const float*)d_in[7];
    const float* fbn    = (const float*)d_in[8];
    float* out = (float*)d_out;

    float* fused  = out;                                          // [4096,128]
    float* feats  = out + (size_t)NROWS*128;                      // [4096,288]
    float* coords = out + (size_t)NROWS*128 + (size_t)NROWS*288;  // [4096,4]

    const int FPS_SMEM = CMPN * sizeof(float4);   // 128 KB
    cudaFuncSetAttribute(fps_kernel, cudaFuncAttributeMaxDynamicSharedMemorySize, FPS_SMEM);

    prep_pts_kernel<<<BATCH*NPTS/512, 512>>>(points);
    fps_kernel<<<6, 256, FPS_SMEM>>>(points, rng, coords);
    scan_kernel<<<NROWS/32, 512>>>();
    fusion_kernel<<<NROWS/4, 128>>>(sf, sa_w0, sa_bn0, sa_w1, sa_bn1, fw, fbn, feats, fused);
}